// round 5
// baseline (speedup 1.0000x reference)
#include <cuda_runtime.h>
#include <cstdint>

// KANLinear fused as one tf32 mma.sync GEMM (plain sm_103 target — no tcgen05):
//   out[32768,256] = A[32768,2304] @ W[256,2304]^T
//   A = [ silu(x) | b_splines(x) flat ],  W = [ base_weight | spline_weight*scaler ]
// CTA: BM=128 rows x BN=256 cols, 8 warps (2 m x 4 n), warp tile 64x64,
// K in 72 chunks of 32, double-buffered SMEM in mma-fragment-native layout
// with padded strides so all LDS/STS are bank-conflict-free.

#define TPB 256
#define NCHUNK 72
// A layout: [mfrag 0..7][kstep 0..3][reg 0..3][lane 0..31], strides padded:
#define A_OFF(mf,ks,rg,ln) ((mf)*546 + (ks)*132 + (rg)*33 + (ln))
#define A_WORDS 4368    // 8*546
// B layout: [nfrag 0..31][kstep 0..3][reg 0..1][lane 0..31]:
#define B_OFF(nf,ks,rg,ln) ((nf)*265 + (ks)*66 + (rg)*33 + (ln))
#define B_WORDS 8480    // 32*265
#define SMEM_BYTES ((2*A_WORDS + 2*B_WORDS) * 4)   // 102784

static __device__ __forceinline__ float tf32_rn(float f) {
    uint32_t u;
    asm("cvt.rna.tf32.f32 %0, %1;" : "=r"(u) : "f"(f));
    return __uint_as_float(u);
}

static __device__ __forceinline__ void gen_chunk(
    int c, float* __restrict__ sA, float* __restrict__ sB,
    int rbase, int tid,
    const float* __restrict__ X, const float* __restrict__ BW,
    const float* __restrict__ SW, const float* __restrict__ SS,
    const float* __restrict__ sg,
    const float (*__restrict__ siL)[10], const float (*__restrict__ siR)[10])
{
    // ---------------- A tile: 128 rows x 32 k ----------------
    {
        const int r     = tid & 127;
        const int h     = tid >> 7;          // which 16-k half this thread fills
        const int mf    = r >> 4;
        const int rhalf = (r >> 3) & 1;
        const int lnb   = (r & 7) * 4;
        if (c < 8) {
            const float4* xp = reinterpret_cast<const float4*>(
                X + (size_t)(rbase + r) * 256 + c * 32 + h * 16);
            float4 v0 = xp[0], v1 = xp[1], v2 = xp[2], v3 = xp[3];
            float xs[16] = { v0.x, v0.y, v0.z, v0.w, v1.x, v1.y, v1.z, v1.w,
                             v2.x, v2.y, v2.z, v2.w, v3.x, v3.y, v3.z, v3.w };
#pragma unroll
            for (int u = 0; u < 16; ++u) {
                float x = xs[u];
                float s = tf32_rn(x / (1.0f + __expf(-x)));
                int kk = h * 16 + u;
                sA[A_OFF(mf, kk >> 3, rhalf + 2 * ((kk >> 2) & 1), lnb + (kk & 3))] = s;
            }
        } else {
            const int f0 = (c - 8) * 4;
            float2 xv = *reinterpret_cast<const float2*>(
                X + (size_t)(rbase + r) * 256 + f0 + 2 * h);
#pragma unroll
            for (int qi = 0; qi < 2; ++qi) {
                float x = qi ? xv.y : xv.x;
                float bs[11];
#pragma unroll
                for (int j = 0; j < 11; ++j)
                    bs[j] = (x >= sg[j] && x < sg[j + 1]) ? 1.0f : 0.0f;
#pragma unroll
                for (int k = 1; k <= 3; ++k) {
#pragma unroll
                    for (int j = 0; j < 10; ++j) {
                        if (j <= 10 - k)
                            bs[j] = (x - sg[j]) * siL[k - 1][j] * bs[j]
                                  + (sg[j + k + 1] - x) * siR[k - 1][j] * bs[j + 1];
                    }
                }
#pragma unroll
                for (int j = 0; j < 8; ++j) {
                    int kk = h * 16 + qi * 8 + j;
                    sA[A_OFF(mf, kk >> 3, rhalf + 2 * ((kk >> 2) & 1), lnb + (kk & 3))]
                        = tf32_rn(bs[j]);
                }
            }
        }
    }
    // ---------------- W tile: 256 n x 32 k (coalesced loads) ----------------
    if (c < 8) {
#pragma unroll
        for (int p = 0; p < 8; ++p) {
            int F = p * 256 + tid;
            int n = F >> 3, fo = F & 7;
            float4 w = *reinterpret_cast<const float4*>(
                BW + (size_t)n * 256 + c * 32 + fo * 4);
            float ws[4] = { w.x, w.y, w.z, w.w };
            int nf = n >> 3, lb = (n & 7) * 4;
#pragma unroll
            for (int e = 0; e < 4; ++e) {
                int kk = fo * 4 + e;
                sB[B_OFF(nf, kk >> 3, (kk >> 2) & 1, lb + (kk & 3))] = tf32_rn(ws[e]);
            }
        }
    } else {
        const int f0 = (c - 8) * 4;
#pragma unroll
        for (int p = 0; p < 8; ++p) {
            int F = p * 256 + tid;
            int n = F >> 3, fo = F & 7;
            float sc = SS[(size_t)n * 256 + f0 + (fo >> 1)];
            float4 w = *reinterpret_cast<const float4*>(
                SW + ((size_t)n * 256 + f0) * 8 + fo * 4);
            float ws[4] = { w.x, w.y, w.z, w.w };
            int nf = n >> 3, lb = (n & 7) * 4;
#pragma unroll
            for (int e = 0; e < 4; ++e) {
                int kk = fo * 4 + e;
                sB[B_OFF(nf, kk >> 3, (kk >> 2) & 1, lb + (kk & 3))] = tf32_rn(ws[e] * sc);
            }
        }
    }
}

__global__ void __launch_bounds__(TPB, 1) kan_kernel(
    const float* __restrict__ X,    // [32768,256]
    const float* __restrict__ BW,   // [256,256]
    const float* __restrict__ SW,   // [256,256,8]
    const float* __restrict__ SS,   // [256,256]
    const float* __restrict__ G,    // [12]
    float* __restrict__ OUT)        // [32768,256]
{
    extern __shared__ float sm[];
    __shared__ float s_g[12];
    __shared__ float s_iL[3][10];
    __shared__ float s_iR[3][10];

    const int tid  = threadIdx.x;
    const int wid  = tid >> 5;
    const int lane = tid & 31;

    if (tid < 12) s_g[tid] = G[tid];
    __syncthreads();
    if (tid < 30) {
        int k = tid / 10, j = tid % 10;     // k = order-1 (0..2)
        if (j <= 9 - k) {
            s_iL[k][j] = 1.0f / (s_g[j + k + 1] - s_g[j]);
            s_iR[k][j] = 1.0f / (s_g[j + k + 2] - s_g[j + 1]);
        }
    }
    __syncthreads();

    const int rbase  = blockIdx.x * 128;
    const int warp_m = wid & 1;
    const int warp_n = wid >> 1;

    float acc[4][8][4];
#pragma unroll
    for (int mf = 0; mf < 4; ++mf)
#pragma unroll
        for (int nf = 0; nf < 8; ++nf)
#pragma unroll
            for (int rr = 0; rr < 4; ++rr) acc[mf][nf][rr] = 0.0f;

    gen_chunk(0, sm, sm + 2 * A_WORDS, rbase, tid, X, BW, SW, SS, s_g, s_iL, s_iR);
    __syncthreads();

    for (int c = 0; c < NCHUNK; ++c) {
        const int b = c & 1;
        if (c + 1 < NCHUNK)
            gen_chunk(c + 1,
                      sm + ((c + 1) & 1) * A_WORDS,
                      sm + 2 * A_WORDS + ((c + 1) & 1) * B_WORDS,
                      rbase, tid, X, BW, SW, SS, s_g, s_iL, s_iR);

        const float* bufA = sm + b * A_WORDS;
        const float* bufB = sm + 2 * A_WORDS + b * B_WORDS;

#pragma unroll
        for (int ks = 0; ks < 4; ++ks) {
            uint32_t a[4][4];
#pragma unroll
            for (int mf = 0; mf < 4; ++mf) {
                const int base = A_OFF(warp_m * 4 + mf, ks, 0, lane);
#pragma unroll
                for (int rg = 0; rg < 4; ++rg)
                    a[mf][rg] = __float_as_uint(bufA[base + rg * 33]);
            }
#pragma unroll
            for (int nf = 0; nf < 8; ++nf) {
                const int bb = B_OFF(warp_n * 8 + nf, ks, 0, lane);
                const uint32_t b0 = __float_as_uint(bufB[bb]);
                const uint32_t b1 = __float_as_uint(bufB[bb + 33]);
#pragma unroll
                for (int mf = 0; mf < 4; ++mf) {
                    asm volatile(
                        "mma.sync.aligned.m16n8k8.row.col.f32.tf32.tf32.f32 "
                        "{%0,%1,%2,%3}, {%4,%5,%6,%7}, {%8,%9}, {%0,%1,%2,%3};"
                        : "+f"(acc[mf][nf][0]), "+f"(acc[mf][nf][1]),
                          "+f"(acc[mf][nf][2]), "+f"(acc[mf][nf][3])
                        : "r"(a[mf][0]), "r"(a[mf][1]), "r"(a[mf][2]), "r"(a[mf][3]),
                          "r"(b0), "r"(b1));
                }
            }
        }
        __syncthreads();
    }

    // ---------------- epilogue: registers -> GMEM ----------------
    const int g = lane >> 2, t = lane & 3;
#pragma unroll
    for (int mf = 0; mf < 4; ++mf) {
#pragma unroll
        for (int nf = 0; nf < 8; ++nf) {
            const int row = rbase + warp_m * 64 + mf * 16 + g;
            const int col = warp_n * 64 + nf * 8 + t * 2;
            float2 lo; lo.x = acc[mf][nf][0]; lo.y = acc[mf][nf][1];
            float2 hi; hi.x = acc[mf][nf][2]; hi.y = acc[mf][nf][3];
            *reinterpret_cast<float2*>(OUT + (size_t)row * 256 + col) = lo;
            *reinterpret_cast<float2*>(OUT + (size_t)(row + 8) * 256 + col) = hi;
        }
    }
}

extern "C" void kernel_launch(void* const* d_in, const int* in_sizes, int n_in,
                              void* d_out, int out_size) {
    const float* X  = (const float*)d_in[0];
    const float* BW = (const float*)d_in[1];
    const float* SW = (const float*)d_in[2];
    const float* SS = (const float*)d_in[3];
    const float* G  = (const float*)d_in[4];
    float* OUT = (float*)d_out;
    (void)in_sizes; (void)n_in; (void)out_size;

    cudaFuncSetAttribute(kan_kernel, cudaFuncAttributeMaxDynamicSharedMemorySize,
                         SMEM_BYTES);
    kan_kernel<<<256, TPB, SMEM_BYTES>>>(X, BW, SW, SS, G, OUT);
}